// round 1
// baseline (speedup 1.0000x reference)
#include <cuda_runtime.h>
#include <cstdint>
#include <cstddef>

// Problem constants
#define BB    4
#define TT    4096
#define CC    512
#define HH    64
#define BT    (BB * TT)            // 16384 rows
#define QTILE 128                  // queries per attention block
#define NQT   (TT / QTILE)         // 32 query tiles per batch
#define CHUNK 512                  // keys per split-K chunk
#define MAXCH (TT / CHUNK)         // 8 chunks max
#define KT    32                   // keys per smem tile

// Scratch (allocation-free rule: __device__ globals)
__device__ float g_K[BT * HH];                                     // x @ Wk  (query role)
__device__ float g_Q[BT * HH];                                     // x @ Wq  (key role)
__device__ float g_V[BT * HH];                                     // x @ Wv
__device__ float g_po[(size_t)BB * NQT * MAXCH * QTILE * HH];      // split-K partial O
__device__ float g_pm[BB * NQT * MAXCH * QTILE];                   // partial running max (base-2 domain)
__device__ float g_pl[BB * NQT * MAXCH * QTILE];                   // partial sum of exps

__device__ __forceinline__ float ex2f(float x) {
    float y;
    asm("ex2.approx.ftz.f32 %0, %1;" : "=f"(y) : "f"(x));
    return y;
}

// ---------------------------------------------------------------------------
// Projection: out[row, 0:64] = x[row, :] @ W    for W in {Wk, Wq, Wv}
// grid = (BT/64, 3), block = 256.  Each block: 64 rows x 64 cols, k-tiled by 32.
// ---------------------------------------------------------------------------
__global__ void __launch_bounds__(256) proj_kernel(
    const float* __restrict__ x,
    const float* __restrict__ Wk,
    const float* __restrict__ Wq,
    const float* __restrict__ Wv)
{
    __shared__ float xs[64][33];   // [row][k] padded
    __shared__ float Ws[32][64];   // [k][col]

    const float* W;
    float* out;
    if (blockIdx.y == 0)      { W = Wk; out = g_K; }
    else if (blockIdx.y == 1) { W = Wq; out = g_Q; }
    else                      { W = Wv; out = g_V; }

    const int tid = threadIdx.x;
    const int tx = tid & 15;         // col group (4 cols)
    const int ty = tid >> 4;         // row group (4 rows)
    const int row0 = blockIdx.x * 64;

    float acc[4][4];
    #pragma unroll
    for (int i = 0; i < 4; i++)
        #pragma unroll
        for (int j = 0; j < 4; j++) acc[i][j] = 0.f;

    for (int kb = 0; kb < CC; kb += 32) {
        __syncthreads();
        // load x tile [64 rows x 32 k] (coalesced along k)
        for (int i = tid; i < 64 * 32; i += 256) {
            int r = i >> 5, kk = i & 31;
            xs[r][kk] = x[(size_t)(row0 + r) * CC + kb + kk];
        }
        // load W tile [32 k x 64 cols] (coalesced along cols)
        for (int i = tid; i < 32 * 64; i += 256) {
            int k = i >> 6, cc = i & 63;
            Ws[k][cc] = W[(size_t)(kb + k) * HH + cc];
        }
        __syncthreads();

        #pragma unroll 8
        for (int k = 0; k < 32; k++) {
            float4 bb = *(const float4*)&Ws[k][tx * 4];
            float a0 = xs[ty * 4 + 0][k];
            float a1 = xs[ty * 4 + 1][k];
            float a2 = xs[ty * 4 + 2][k];
            float a3 = xs[ty * 4 + 3][k];
            acc[0][0] = fmaf(a0, bb.x, acc[0][0]);
            acc[0][1] = fmaf(a0, bb.y, acc[0][1]);
            acc[0][2] = fmaf(a0, bb.z, acc[0][2]);
            acc[0][3] = fmaf(a0, bb.w, acc[0][3]);
            acc[1][0] = fmaf(a1, bb.x, acc[1][0]);
            acc[1][1] = fmaf(a1, bb.y, acc[1][1]);
            acc[1][2] = fmaf(a1, bb.z, acc[1][2]);
            acc[1][3] = fmaf(a1, bb.w, acc[1][3]);
            acc[2][0] = fmaf(a2, bb.x, acc[2][0]);
            acc[2][1] = fmaf(a2, bb.y, acc[2][1]);
            acc[2][2] = fmaf(a2, bb.z, acc[2][2]);
            acc[2][3] = fmaf(a2, bb.w, acc[2][3]);
            acc[3][0] = fmaf(a3, bb.x, acc[3][0]);
            acc[3][1] = fmaf(a3, bb.y, acc[3][1]);
            acc[3][2] = fmaf(a3, bb.z, acc[3][2]);
            acc[3][3] = fmaf(a3, bb.w, acc[3][3]);
        }
    }

    #pragma unroll
    for (int i = 0; i < 4; i++) {
        float4 v = make_float4(acc[i][0], acc[i][1], acc[i][2], acc[i][3]);
        *(float4*)&out[(size_t)(row0 + ty * 4 + i) * HH + tx * 4] = v;
    }
}

// ---------------------------------------------------------------------------
// Split-K flash attention partial.
// grid = (MAXCH, NQT, B), block = 128 threads (one query per thread).
// Q-role = g_K, K-role = g_Q, V = g_V.  Scores pre-scaled into base-2 domain.
// ---------------------------------------------------------------------------
__global__ void __launch_bounds__(128) attn_partial()
{
    const int cI = blockIdx.x;
    const int qt = blockIdx.y;
    const int b  = blockIdx.z;
    const int qb = qt * QTILE;
    const int kstart = cI * CHUNK;
    if (kstart >= qb + QTILE) return;                     // chunk beyond causal range
    const int kend = min(kstart + CHUNK, qb + QTILE);

    const int tid = threadIdx.x;
    const int t = qb + tid;                               // this thread's query row

    __shared__ float Ks[KT][HH];
    __shared__ float Vs[KT][HH];
    __shared__ float Ssm[QTILE][KT + 1];                  // padded: stride 33

    // load query row, fold scale * log2(e) into it
    const float SC = (float)(1.4426950408889634 * 0.044194173824159216); // log2e / sqrt(512)
    float q[HH], o[HH];
    {
        const float4* qp = (const float4*)(g_K + ((size_t)b * TT + t) * HH);
        #pragma unroll
        for (int d4 = 0; d4 < 16; d4++) {
            float4 v = qp[d4];
            q[d4 * 4 + 0] = v.x * SC;
            q[d4 * 4 + 1] = v.y * SC;
            q[d4 * 4 + 2] = v.z * SC;
            q[d4 * 4 + 3] = v.w * SC;
            o[d4 * 4 + 0] = 0.f; o[d4 * 4 + 1] = 0.f;
            o[d4 * 4 + 2] = 0.f; o[d4 * 4 + 3] = 0.f;
        }
    }
    float m = -1e30f, l = 0.f;

    for (int kb = kstart; kb < kend; kb += KT) {
        __syncthreads();  // previous tile consumers done
        {
            const float4* kg = (const float4*)(g_Q + ((size_t)b * TT + kb) * HH);
            const float4* vg = (const float4*)(g_V + ((size_t)b * TT + kb) * HH);
            #pragma unroll
            for (int i = tid; i < KT * 16; i += 128) {
                ((float4*)Ks)[i] = kg[i];
                ((float4*)Vs)[i] = vg[i];
            }
        }
        __syncthreads();

        // score phase: S[tid][j] = q . K[j]  (base-2 scaled), track tile max
        float mt = -1e30f;
        for (int j = 0; j < KT; j++) {
            float s0 = 0.f, s1 = 0.f, s2 = 0.f, s3 = 0.f;
            #pragma unroll
            for (int d4 = 0; d4 < 16; d4++) {
                float4 kk = ((const float4*)Ks[j])[d4];
                s0 = fmaf(q[d4 * 4 + 0], kk.x, s0);
                s1 = fmaf(q[d4 * 4 + 1], kk.y, s1);
                s2 = fmaf(q[d4 * 4 + 2], kk.z, s2);
                s3 = fmaf(q[d4 * 4 + 3], kk.w, s3);
            }
            float s = (s0 + s1) + (s2 + s3);
            if (kb + j > t) s = -1e30f;                   // causal mask
            Ssm[tid][j] = s;
            mt = fmaxf(mt, s);
        }

        // online-softmax rescale (only when the max improves)
        if (mt > m) {
            float alpha = ex2f(m - mt);                   // m == -1e30 -> alpha == 0
            l *= alpha;
            #pragma unroll
            for (int d = 0; d < HH; d++) o[d] *= alpha;
            m = mt;
        }

        // accumulate phase: p = 2^(s - m); o += p * V[j]
        #pragma unroll 2
        for (int j = 0; j < KT; j++) {
            float p = ex2f(Ssm[tid][j] - m);
            l += p;
            #pragma unroll
            for (int d4 = 0; d4 < 16; d4++) {
                float4 vv = ((const float4*)Vs[j])[d4];
                o[d4 * 4 + 0] = fmaf(p, vv.x, o[d4 * 4 + 0]);
                o[d4 * 4 + 1] = fmaf(p, vv.y, o[d4 * 4 + 1]);
                o[d4 * 4 + 2] = fmaf(p, vv.z, o[d4 * 4 + 2]);
                o[d4 * 4 + 3] = fmaf(p, vv.w, o[d4 * 4 + 3]);
            }
        }
    }

    // write split-K partials
    const size_t pbase = ((size_t)((b * NQT + qt) * MAXCH + cI)) * QTILE + tid;
    g_pm[pbase] = m;
    g_pl[pbase] = l;
    float4* po = (float4*)(g_po + pbase * HH);
    #pragma unroll
    for (int d4 = 0; d4 < 16; d4++)
        po[d4] = make_float4(o[d4 * 4 + 0], o[d4 * 4 + 1], o[d4 * 4 + 2], o[d4 * 4 + 3]);
}

// ---------------------------------------------------------------------------
// Split-K combine: out[t] = sum_i 2^(m_i - M) * o_i  /  sum_i 2^(m_i - M) * l_i
// grid = (NQT, B), block = 128.
// ---------------------------------------------------------------------------
__global__ void __launch_bounds__(128) combine_kernel(float* __restrict__ out)
{
    const int qt = blockIdx.x;
    const int b  = blockIdx.y;
    const int tid = threadIdx.x;
    const int nch = qt / 4 + 1;    // = ceil(128*(qt+1)/512)

    const size_t pb = ((size_t)((b * NQT + qt) * MAXCH)) * QTILE + tid;

    float M = -1e30f;
    for (int i = 0; i < nch; i++)
        M = fmaxf(M, g_pm[pb + (size_t)i * QTILE]);

    float acc[HH];
    #pragma unroll
    for (int d = 0; d < HH; d++) acc[d] = 0.f;
    float L = 0.f;

    for (int i = 0; i < nch; i++) {
        const size_t pi = pb + (size_t)i * QTILE;
        float w = ex2f(g_pm[pi] - M);
        L = fmaf(w, g_pl[pi], L);
        const float4* po = (const float4*)(g_po + pi * HH);
        #pragma unroll
        for (int d4 = 0; d4 < 16; d4++) {
            float4 v = po[d4];
            acc[d4 * 4 + 0] = fmaf(w, v.x, acc[d4 * 4 + 0]);
            acc[d4 * 4 + 1] = fmaf(w, v.y, acc[d4 * 4 + 1]);
            acc[d4 * 4 + 2] = fmaf(w, v.z, acc[d4 * 4 + 2]);
            acc[d4 * 4 + 3] = fmaf(w, v.w, acc[d4 * 4 + 3]);
        }
    }

    const float invL = 1.f / L;
    float4* op = (float4*)(out + ((size_t)b * TT + qt * QTILE + tid) * HH);
    #pragma unroll
    for (int d4 = 0; d4 < 16; d4++)
        op[d4] = make_float4(acc[d4 * 4 + 0] * invL, acc[d4 * 4 + 1] * invL,
                             acc[d4 * 4 + 2] * invL, acc[d4 * 4 + 3] * invL);
}

// ---------------------------------------------------------------------------
extern "C" void kernel_launch(void* const* d_in, const int* in_sizes, int n_in,
                              void* d_out, int out_size)
{
    const float* x  = (const float*)d_in[0];
    const float* Wk = (const float*)d_in[1];
    const float* Wq = (const float*)d_in[2];
    const float* Wv = (const float*)d_in[3];
    (void)in_sizes; (void)n_in; (void)out_size;

    proj_kernel<<<dim3(BT / 64, 3), 256>>>(x, Wk, Wq, Wv);
    attn_partial<<<dim3(MAXCH, NQT, BB), 128>>>();
    combine_kernel<<<dim3(NQT, BB), 128>>>((float*)d_out);
}

// round 3
// speedup vs baseline: 4.5933x; 4.5933x over previous
#include <cuda_runtime.h>
#include <cuda_fp16.h>
#include <cstdint>
#include <cstddef>

// ---------------- problem constants ----------------
#define BB    4
#define TT    4096
#define CC    512
#define HH    64
#define BT    (BB * TT)
#define QT    128                 // queries per attention block
#define NQT   (TT / QT)           // 32
#define CHUNK 512
#define MAXCH (TT / CHUNK)        // 8
#define KTILE 64                  // keys per tile

// log2(e) / sqrt(512)  (folded into Wk -> scores arrive in base-2 domain)
#define SC2   0.063766600930416f

#define SKS   72                  // halfs per smem row (144 B = 9*16B, conflict-free)

// ---------------- global scratch ----------------
__device__ __half g_K[BT * HH];            // x @ (Wk*SC2)  (query role)
__device__ __half g_Q[BT * HH];            // x @ Wq        (key role)
__device__ __half g_Vt[(size_t)BB * HH * TT]; // (x @ Wv)^T : [b][h][t]
__device__ float  g_po[(size_t)BB * NQT * MAXCH * QT * HH];
__device__ float  g_pl[BB * NQT * MAXCH * QT];

// ---------------- helpers ----------------
__device__ __forceinline__ float ex2f(float x) {
    float y; asm("ex2.approx.ftz.f32 %0, %1;" : "=f"(y) : "f"(x)); return y;
}
__device__ __forceinline__ uint32_t smem_u32(const void* p) {
    uint32_t a;
    asm("{ .reg .u64 t; cvta.to.shared.u64 t, %1; cvt.u32.u64 %0, t; }" : "=r"(a) : "l"(p));
    return a;
}
__device__ __forceinline__ void mma16816(float* d, const uint32_t* a, const uint32_t* b) {
    asm volatile(
        "mma.sync.aligned.m16n8k16.row.col.f32.f16.f16.f32 "
        "{%0,%1,%2,%3}, {%4,%5,%6,%7}, {%8,%9}, {%0,%1,%2,%3};"
        : "+f"(d[0]), "+f"(d[1]), "+f"(d[2]), "+f"(d[3])
        : "r"(a[0]), "r"(a[1]), "r"(a[2]), "r"(a[3]), "r"(b[0]), "r"(b[1]));
}
__device__ __forceinline__ void cpa16(uint32_t dst, const void* src) {
    asm volatile("cp.async.cg.shared.global [%0], [%1], 16;" :: "r"(dst), "l"(src));
}
#define CP_COMMIT() asm volatile("cp.async.commit_group;" ::: "memory")
#define CP_WAIT(n)  asm volatile("cp.async.wait_group %0;" :: "n"(n) : "memory")

__device__ __forceinline__ uint32_t packh2(float a, float b) {
    __half2 h = __floats2half2_rn(a, b);
    return *(uint32_t*)&h;
}

// ===========================================================================
// Projection: D[128 rows x 64] = x_tile @ W   (one W per blockIdx.y)
// 256 threads = 8 warps x 16 rows. fp16 mma, fp32 accum.
// ===========================================================================
__global__ void __launch_bounds__(256) proj_tc(
    const float* __restrict__ x,
    const float* __restrict__ Wk,
    const float* __restrict__ Wq,
    const float* __restrict__ Wv)
{
    __shared__ __half Xs[128 * SKS];   // [row][c]
    __shared__ __half Ws[64 * SKS];    // [h][c]  (transposed W)

    const int y = blockIdx.y;
    const float* W = (y == 0) ? Wk : ((y == 1) ? Wq : Wv);
    const float sc = (y == 0) ? SC2 : 1.0f;
    const int row0 = blockIdx.x * 128;

    const int tid = threadIdx.x, wid = tid >> 5, lane = tid & 31;
    const int lr = lane >> 2, lc = lane & 3;

    float o[8][4];
    #pragma unroll
    for (int j = 0; j < 8; j++)
        #pragma unroll
        for (int i = 0; i < 4; i++) o[j][i] = 0.f;

    for (int kc = 0; kc < 8; kc++) {
        const int kb = kc * 64;
        __syncthreads();
        // x tile [128 x 64] fp32 -> fp16
        #pragma unroll
        for (int it = 0; it < 8; it++) {
            int i = tid + it * 256;
            int r = i >> 4, c4 = i & 15;
            float4 v = *(const float4*)(x + (size_t)(row0 + r) * CC + kb + c4 * 4);
            uint2 u = make_uint2(packh2(v.x, v.y), packh2(v.z, v.w));
            *(uint2*)((char*)Xs + ((size_t)r * SKS + c4 * 4) * 2) = u;
        }
        // W tile transposed: Ws[h][c]
        #pragma unroll
        for (int it = 0; it < 8; it++) {
            int i = tid + it * 256;
            int c = i >> 5, h = (i & 31) * 2;
            float2 v = *(const float2*)(W + (size_t)(kb + c) * HH + h);
            Ws[(size_t)h * SKS + c]       = __float2half_rn(v.x * sc);
            Ws[(size_t)(h + 1) * SKS + c] = __float2half_rn(v.y * sc);
        }
        __syncthreads();

        const int xrow = wid * 16 + lr;
        #pragma unroll
        for (int kk = 0; kk < 4; kk++) {
            uint32_t a[4];
            const __half* xp = Xs + (size_t)xrow * SKS + kk * 16 + lc * 2;
            a[0] = *(const uint32_t*)xp;
            a[1] = *(const uint32_t*)(xp + 8 * SKS);
            a[2] = *(const uint32_t*)(xp + 8);
            a[3] = *(const uint32_t*)(xp + 8 * SKS + 8);
            #pragma unroll
            for (int hj = 0; hj < 8; hj++) {
                uint32_t b[2];
                const __half* wp = Ws + (size_t)(hj * 8 + lr) * SKS + kk * 16 + lc * 2;
                b[0] = *(const uint32_t*)wp;
                b[1] = *(const uint32_t*)(wp + 8);
                mma16816(o[hj], a, b);
            }
        }
    }

    // epilogue
    const int r = row0 + wid * 16 + lr;
    if (y < 2) {
        __half* out = (y == 0) ? g_K : g_Q;
        #pragma unroll
        for (int hj = 0; hj < 8; hj++) {
            int h = hj * 8 + lc * 2;
            *(uint32_t*)(out + (size_t)r * HH + h)       = packh2(o[hj][0], o[hj][1]);
            *(uint32_t*)(out + (size_t)(r + 8) * HH + h) = packh2(o[hj][2], o[hj][3]);
        }
    } else {
        const int bb = r >> 12, t = r & 4095;
        #pragma unroll
        for (int hj = 0; hj < 8; hj++) {
            int h = hj * 8 + lc * 2;
            g_Vt[((size_t)bb * HH + h) * TT + t]         = __float2half_rn(o[hj][0]);
            g_Vt[((size_t)bb * HH + h + 1) * TT + t]     = __float2half_rn(o[hj][1]);
            g_Vt[((size_t)bb * HH + h) * TT + t + 8]     = __float2half_rn(o[hj][2]);
            g_Vt[((size_t)bb * HH + h + 1) * TT + t + 8] = __float2half_rn(o[hj][3]);
        }
    }
}

// ===========================================================================
// Attention partial: grid (MAXCH, NQT, BB), 256 threads (8 warps x 16 rows).
// S = K_proj . Q_proj^T (fp16 mma), no online max, P fp16, O fp32 accum.
// ===========================================================================
__global__ void __launch_bounds__(256) attn_tc()
{
    const int cI = blockIdx.x, qt = blockIdx.y, b = blockIdx.z;
    const int qb = qt * QT;
    const int kstart = cI * CHUNK;
    if (kstart >= qb + QT) return;
    const int kend = min(kstart + CHUNK, qb + QT);

    __shared__ __half Ks[2][64 * SKS];   // [key][h]
    __shared__ __half Vs[2][64 * SKS];   // [h][key]

    const int tid = threadIdx.x, wid = tid >> 5, lane = tid & 31;
    const int lr = lane >> 2, lc = lane & 3;
    const int r0 = qb + wid * 16 + lr;           // query rows r0, r0+8

    // Q a-fragments, register-resident for the whole chunk
    uint32_t aq[4][4];
    {
        const __half* q0 = g_K + ((size_t)b * TT + r0) * HH;
        #pragma unroll
        for (int kk = 0; kk < 4; kk++) {
            int h0 = kk * 16 + lc * 2;
            aq[kk][0] = *(const uint32_t*)(q0 + h0);
            aq[kk][1] = *(const uint32_t*)(q0 + 8 * HH + h0);
            aq[kk][2] = *(const uint32_t*)(q0 + h0 + 8);
            aq[kk][3] = *(const uint32_t*)(q0 + 8 * HH + h0 + 8);
        }
    }

    float o[8][4];
    #pragma unroll
    for (int j = 0; j < 8; j++)
        #pragma unroll
        for (int i = 0; i < 4; i++) o[j][i] = 0.f;
    float l0 = 0.f, l1 = 0.f;

    const uint32_t ksa0 = smem_u32(Ks[0]), ksa1 = smem_u32(Ks[1]);
    const uint32_t vsa0 = smem_u32(Vs[0]), vsa1 = smem_u32(Vs[1]);

    // prefetch helper (2 K segs + 2 V segs per thread)
    auto prefetch = [&](int buf, int kb) {
        const uint32_t ka = buf ? ksa1 : ksa0;
        const uint32_t va = buf ? vsa1 : vsa0;
        #pragma unroll
        for (int it = 0; it < 2; it++) {
            int i = tid + it * 256;
            int row = i >> 3, seg = i & 7;
            cpa16(ka + ((uint32_t)row * SKS + seg * 8) * 2,
                  g_Q + ((size_t)b * TT + kb + row) * HH + seg * 8);
            cpa16(va + ((uint32_t)row * SKS + seg * 8) * 2,
                  g_Vt + ((size_t)b * HH + row) * TT + kb + seg * 8);
        }
    };

    prefetch(0, kstart);
    CP_COMMIT();

    int buf = 0;
    for (int kb = kstart; kb < kend; kb += KTILE) {
        const bool havenext = (kb + KTILE < kend);
        if (havenext) { prefetch(buf ^ 1, kb + KTILE); CP_COMMIT(); CP_WAIT(1); }
        else          { CP_WAIT(0); }
        __syncthreads();

        const __half* ks = Ks[buf];
        const __half* vs = Vs[buf];

        #pragma unroll
        for (int kt2 = 0; kt2 < 4; kt2++) {
            float s[2][4];
            #pragma unroll
            for (int jj = 0; jj < 2; jj++) {
                s[jj][0] = 0.f; s[jj][1] = 0.f; s[jj][2] = 0.f; s[jj][3] = 0.f;
                const int j = kt2 * 2 + jj;
                #pragma unroll
                for (int kk = 0; kk < 4; kk++) {
                    uint32_t bk[2];
                    const __half* kp = ks + (size_t)(j * 8 + lr) * SKS + kk * 16 + lc * 2;
                    bk[0] = *(const uint32_t*)kp;
                    bk[1] = *(const uint32_t*)(kp + 8);
                    mma16816(s[jj], aq[kk], bk);
                }
            }
            // softmax (no max): exp2, causal mask, pack to PV A-fragment
            uint32_t pa[4];
            #pragma unroll
            for (int jj = 0; jj < 2; jj++) {
                const int c0 = kb + kt2 * 16 + jj * 8 + lc * 2;
                float e0 = (c0     <= r0)     ? ex2f(s[jj][0]) : 0.f;
                float e1 = (c0 + 1 <= r0)     ? ex2f(s[jj][1]) : 0.f;
                float e2 = (c0     <= r0 + 8) ? ex2f(s[jj][2]) : 0.f;
                float e3 = (c0 + 1 <= r0 + 8) ? ex2f(s[jj][3]) : 0.f;
                l0 += e0 + e1;
                l1 += e2 + e3;
                pa[jj * 2 + 0] = packh2(e0, e1);
                pa[jj * 2 + 1] = packh2(e2, e3);
            }
            // wait: A-frag needs {a0,a1} = k rows 0-7 halves, {a2,a3} = k rows 8-15
            // pa[0]=jj0(c0,c1) pa[1]=jj0(c2,c3) pa[2]=jj1(c0,c1) pa[3]=jj1(c2,c3)  -- correct mapping
            #pragma unroll
            for (int hj = 0; hj < 8; hj++) {
                uint32_t bv[2];
                const __half* vp = vs + (size_t)(hj * 8 + lr) * SKS + kt2 * 16 + lc * 2;
                bv[0] = *(const uint32_t*)vp;
                bv[1] = *(const uint32_t*)(vp + 8);
                mma16816(o[hj], pa, bv);
            }
        }
        __syncthreads();   // compute done before next prefetch overwrites
        buf ^= 1;
    }

    // reduce row sums across the 4 lanes sharing a row
    l0 += __shfl_xor_sync(0xFFFFFFFFu, l0, 1);
    l0 += __shfl_xor_sync(0xFFFFFFFFu, l0, 2);
    l1 += __shfl_xor_sync(0xFFFFFFFFu, l1, 1);
    l1 += __shfl_xor_sync(0xFFFFFFFFu, l1, 2);

    const size_t pbase = ((size_t)((b * NQT + qt) * MAXCH + cI)) * QT;
    const int rl = wid * 16 + lr;
    if (lc == 0) {
        g_pl[pbase + rl]     = l0;
        g_pl[pbase + rl + 8] = l1;
    }
    #pragma unroll
    for (int hj = 0; hj < 8; hj++) {
        int h = hj * 8 + lc * 2;
        *(float2*)(g_po + (pbase + rl) * HH + h)     = make_float2(o[hj][0], o[hj][1]);
        *(float2*)(g_po + (pbase + rl + 8) * HH + h) = make_float2(o[hj][2], o[hj][3]);
    }
}

// ===========================================================================
// Combine: out = (sum_i o_i) / (sum_i l_i)
// ===========================================================================
__global__ void __launch_bounds__(128) combine_kernel(float* __restrict__ out)
{
    const int qt = blockIdx.x, b = blockIdx.y;
    const int tid = threadIdx.x;
    const int nch = qt / 4 + 1;

    const size_t pb = ((size_t)((b * NQT + qt) * MAXCH)) * QT + tid;
    float acc[HH];
    #pragma unroll
    for (int d = 0; d < HH; d++) acc[d] = 0.f;
    float L = 0.f;

    for (int i = 0; i < nch; i++) {
        const size_t pi = pb + (size_t)i * QT;
        L += g_pl[pi];
        const float4* po = (const float4*)(g_po + pi * HH);
        #pragma unroll
        for (int d4 = 0; d4 < 16; d4++) {
            float4 v = po[d4];
            acc[d4*4+0] += v.x; acc[d4*4+1] += v.y;
            acc[d4*4+2] += v.z; acc[d4*4+3] += v.w;
        }
    }
    const float invL = 1.f / L;
    float4* op = (float4*)(out + ((size_t)b * TT + qt * QT + tid) * HH);
    #pragma unroll
    for (int d4 = 0; d4 < 16; d4++)
        op[d4] = make_float4(acc[d4*4+0] * invL, acc[d4*4+1] * invL,
                             acc[d4*4+2] * invL, acc[d4*4+3] * invL);
}

// ===========================================================================
extern "C" void kernel_launch(void* const* d_in, const int* in_sizes, int n_in,
                              void* d_out, int out_size)
{
    const float* x  = (const float*)d_in[0];
    const float* Wk = (const float*)d_in[1];
    const float* Wq = (const float*)d_in[2];
    const float* Wv = (const float*)d_in[3];
    (void)in_sizes; (void)n_in; (void)out_size;

    proj_tc<<<dim3(BT / 128, 3), 256>>>(x, Wk, Wq, Wv);
    attn_tc<<<dim3(MAXCH, NQT, BB), 256>>>();
    combine_kernel<<<dim3(NQT, BB), 128>>>((float*)d_out);
}

// round 4
// speedup vs baseline: 5.6828x; 1.2372x over previous
#include <cuda_runtime.h>
#include <cuda_fp16.h>
#include <cstdint>
#include <cstddef>

// ---------------- problem constants ----------------
#define BB    4
#define TT    4096
#define CC    512
#define HH    64
#define BT    (BB * TT)
#define QT    128                 // queries per attention block
#define NQT   (TT / QT)           // 32
#define CHUNK 512
#define MAXCH (TT / CHUNK)        // 8
#define KTILE 64                  // keys per tile

// log2(e) / sqrt(512)  (folded into Wk -> scores arrive in base-2 domain)
#define SC2   0.063766600930416f

#define SKS   72                  // halfs per smem row (144 B, conflict-free)

// ---------------- global scratch ----------------
__device__ __half g_K[BT * HH];               // x @ (Wk*SC2)  (query role)
__device__ __half g_Q[BT * HH];               // x @ Wq        (key role)
__device__ __half g_Vt[(size_t)BB * HH * TT]; // (x @ Wv)^T : [b][h][t]
__device__ __half g_Wt[192 * CC];             // fp16 W^T: [outcol 0-63=K,64-127=Q,128-191=V][c]
__device__ float  g_po[(size_t)BB * NQT * MAXCH * QT * HH];
__device__ float  g_pl[BB * NQT * MAXCH * QT];

// ---------------- helpers ----------------
__device__ __forceinline__ float ex2f(float x) {
    float y; asm("ex2.approx.ftz.f32 %0, %1;" : "=f"(y) : "f"(x)); return y;
}
__device__ __forceinline__ uint32_t smem_u32(const void* p) {
    uint32_t a;
    asm("{ .reg .u64 t; cvta.to.shared.u64 t, %1; cvt.u32.u64 %0, t; }" : "=r"(a) : "l"(p));
    return a;
}
__device__ __forceinline__ void mma16816(float* d, const uint32_t* a, const uint32_t* b) {
    asm volatile(
        "mma.sync.aligned.m16n8k16.row.col.f32.f16.f16.f32 "
        "{%0,%1,%2,%3}, {%4,%5,%6,%7}, {%8,%9}, {%0,%1,%2,%3};"
        : "+f"(d[0]), "+f"(d[1]), "+f"(d[2]), "+f"(d[3])
        : "r"(a[0]), "r"(a[1]), "r"(a[2]), "r"(a[3]), "r"(b[0]), "r"(b[1]));
}
__device__ __forceinline__ void cpa16(uint32_t dst, const void* src) {
    asm volatile("cp.async.cg.shared.global [%0], [%1], 16;" :: "r"(dst), "l"(src));
}
#define CP_COMMIT() asm volatile("cp.async.commit_group;" ::: "memory")
#define CP_WAIT(n)  asm volatile("cp.async.wait_group %0;" :: "n"(n) : "memory")

__device__ __forceinline__ uint32_t packh2(float a, float b) {
    __half2 h = __floats2half2_rn(a, b);
    return *(uint32_t*)&h;
}

// ===========================================================================
// prep_w: fp32 W[c][h] -> fp16 g_Wt[m*64+h][c], SC2 folded into Wk.
// grid (8, 3), block 256.
// ===========================================================================
__global__ void __launch_bounds__(256) prep_w(
    const float* __restrict__ Wk,
    const float* __restrict__ Wq,
    const float* __restrict__ Wv)
{
    const int m = blockIdx.y;
    const int cb = blockIdx.x * 64;
    const float* W = (m == 0) ? Wk : ((m == 1) ? Wq : Wv);
    const float sc = (m == 0) ? SC2 : 1.0f;
    for (int i = threadIdx.x; i < 4096; i += 256) {
        int c = i >> 6, h = i & 63;
        g_Wt[(size_t)(m * 64 + h) * CC + cb + c] =
            __float2half_rn(W[(size_t)(cb + c) * HH + h] * sc);
    }
}

// ===========================================================================
// proj_fused: block = 64 rows x 192 cols (K|Q|V), 256 threads = 8 warps.
// warp (rg, ch): rows rg*16..+15, cols ch*96..+95 (12 n-tiles of 8).
// ===========================================================================
__global__ void __launch_bounds__(256) proj_fused(const float* __restrict__ x)
{
    __shared__ __half Xs[64 * SKS];    // [row][c]
    __shared__ __half Ws[192 * SKS];   // [outcol][c]

    const int tid = threadIdx.x, wid = tid >> 5, lane = tid & 31;
    const int lr = lane >> 2, lc = lane & 3;
    const int rg = wid >> 1, ch = wid & 1;
    const int row0 = blockIdx.x * 64;

    float o[12][4];
    #pragma unroll
    for (int j = 0; j < 12; j++)
        #pragma unroll
        for (int i = 0; i < 4; i++) o[j][i] = 0.f;

    const uint32_t wsa = smem_u32(Ws);

    for (int kc = 0; kc < 8; kc++) {
        const int kb = kc * 64;
        __syncthreads();
        // W tiles via cp.async: 192 rows x 8 segs of 16B
        #pragma unroll
        for (int it = 0; it < 6; it++) {
            int u = tid + it * 256;
            int row = u >> 3, seg = u & 7;
            cpa16(wsa + ((uint32_t)row * SKS + seg * 8) * 2,
                  g_Wt + (size_t)row * CC + kb + seg * 8);
        }
        // x tile [64 x 64] fp32 -> fp16
        #pragma unroll
        for (int it = 0; it < 4; it++) {
            int i = tid + it * 256;
            int r = i >> 4, c4 = i & 15;
            float4 v = *(const float4*)(x + (size_t)(row0 + r) * CC + kb + c4 * 4);
            *(uint2*)((char*)Xs + ((size_t)r * SKS + c4 * 4) * 2) =
                make_uint2(packh2(v.x, v.y), packh2(v.z, v.w));
        }
        CP_COMMIT(); CP_WAIT(0);
        __syncthreads();

        const int xrow = rg * 16 + lr;
        #pragma unroll
        for (int kk = 0; kk < 4; kk++) {
            uint32_t a[4];
            const __half* xp = Xs + (size_t)xrow * SKS + kk * 16 + lc * 2;
            a[0] = *(const uint32_t*)xp;
            a[1] = *(const uint32_t*)(xp + 8 * SKS);
            a[2] = *(const uint32_t*)(xp + 8);
            a[3] = *(const uint32_t*)(xp + 8 * SKS + 8);
            #pragma unroll
            for (int hj = 0; hj < 12; hj++) {
                uint32_t b[2];
                const __half* wp = Ws + (size_t)(ch * 96 + hj * 8 + lr) * SKS + kk * 16 + lc * 2;
                b[0] = *(const uint32_t*)wp;
                b[1] = *(const uint32_t*)(wp + 8);
                mma16816(o[hj], a, b);
            }
        }
    }

    // epilogue
    const int r = row0 + rg * 16 + lr;
    const int bb = r >> 12, t = r & 4095;
    #pragma unroll
    for (int hj = 0; hj < 12; hj++) {
        const int g = ch * 96 + hj * 8;
        const int h2 = (g & 63) + lc * 2;
        if (g < 64) {
            *(uint32_t*)(g_K + (size_t)r * HH + h2)       = packh2(o[hj][0], o[hj][1]);
            *(uint32_t*)(g_K + (size_t)(r + 8) * HH + h2) = packh2(o[hj][2], o[hj][3]);
        } else if (g < 128) {
            *(uint32_t*)(g_Q + (size_t)r * HH + h2)       = packh2(o[hj][0], o[hj][1]);
            *(uint32_t*)(g_Q + (size_t)(r + 8) * HH + h2) = packh2(o[hj][2], o[hj][3]);
        } else {
            g_Vt[((size_t)bb * HH + h2) * TT + t]         = __float2half_rn(o[hj][0]);
            g_Vt[((size_t)bb * HH + h2 + 1) * TT + t]     = __float2half_rn(o[hj][1]);
            g_Vt[((size_t)bb * HH + h2) * TT + t + 8]     = __float2half_rn(o[hj][2]);
            g_Vt[((size_t)bb * HH + h2 + 1) * TT + t + 8] = __float2half_rn(o[hj][3]);
        }
    }
}

// ===========================================================================
// Attention partial: grid (MAXCH, NQT, BB), 256 threads (8 warps x 16 rows).
// S = K_proj . Q_proj^T (fp16 mma), no online max, P fp16, O fp32 accum.
// ===========================================================================
__global__ void __launch_bounds__(256) attn_tc()
{
    const int cI = blockIdx.x, qt = blockIdx.y, b = blockIdx.z;
    const int qb = qt * QT;
    const int kstart = cI * CHUNK;
    if (kstart >= qb + QT) return;
    const int kend = min(kstart + CHUNK, qb + QT);

    __shared__ __half Ks[2][64 * SKS];   // [key][h]
    __shared__ __half Vs[2][64 * SKS];   // [h][key]

    const int tid = threadIdx.x, wid = tid >> 5, lane = tid & 31;
    const int lr = lane >> 2, lc = lane & 3;
    const int r0 = qb + wid * 16 + lr;           // query rows r0, r0+8

    uint32_t aq[4][4];
    {
        const __half* q0 = g_K + ((size_t)b * TT + r0) * HH;
        #pragma unroll
        for (int kk = 0; kk < 4; kk++) {
            int h0 = kk * 16 + lc * 2;
            aq[kk][0] = *(const uint32_t*)(q0 + h0);
            aq[kk][1] = *(const uint32_t*)(q0 + 8 * HH + h0);
            aq[kk][2] = *(const uint32_t*)(q0 + h0 + 8);
            aq[kk][3] = *(const uint32_t*)(q0 + 8 * HH + h0 + 8);
        }
    }

    float o[8][4];
    #pragma unroll
    for (int j = 0; j < 8; j++)
        #pragma unroll
        for (int i = 0; i < 4; i++) o[j][i] = 0.f;
    float l0 = 0.f, l1 = 0.f;

    const uint32_t ksa0 = smem_u32(Ks[0]), ksa1 = smem_u32(Ks[1]);
    const uint32_t vsa0 = smem_u32(Vs[0]), vsa1 = smem_u32(Vs[1]);

    auto prefetch = [&](int buf, int kb) {
        const uint32_t ka = buf ? ksa1 : ksa0;
        const uint32_t va = buf ? vsa1 : vsa0;
        #pragma unroll
        for (int it = 0; it < 2; it++) {
            int i = tid + it * 256;
            int row = i >> 3, seg = i & 7;
            cpa16(ka + ((uint32_t)row * SKS + seg * 8) * 2,
                  g_Q + ((size_t)b * TT + kb + row) * HH + seg * 8);
            cpa16(va + ((uint32_t)row * SKS + seg * 8) * 2,
                  g_Vt + ((size_t)b * HH + row) * TT + kb + seg * 8);
        }
    };

    prefetch(0, kstart);
    CP_COMMIT();

    int buf = 0;
    for (int kb = kstart; kb < kend; kb += KTILE) {
        const bool havenext = (kb + KTILE < kend);
        if (havenext) { prefetch(buf ^ 1, kb + KTILE); CP_COMMIT(); CP_WAIT(1); }
        else          { CP_WAIT(0); }
        __syncthreads();

        const __half* ks = Ks[buf];
        const __half* vs = Vs[buf];

        #pragma unroll
        for (int kt2 = 0; kt2 < 4; kt2++) {
            float s[2][4];
            #pragma unroll
            for (int jj = 0; jj < 2; jj++) {
                s[jj][0] = 0.f; s[jj][1] = 0.f; s[jj][2] = 0.f; s[jj][3] = 0.f;
                const int j = kt2 * 2 + jj;
                #pragma unroll
                for (int kk = 0; kk < 4; kk++) {
                    uint32_t bk[2];
                    const __half* kp = ks + (size_t)(j * 8 + lr) * SKS + kk * 16 + lc * 2;
                    bk[0] = *(const uint32_t*)kp;
                    bk[1] = *(const uint32_t*)(kp + 8);
                    mma16816(s[jj], aq[kk], bk);
                }
            }
            uint32_t pa[4];
            #pragma unroll
            for (int jj = 0; jj < 2; jj++) {
                const int c0 = kb + kt2 * 16 + jj * 8 + lc * 2;
                float e0 = (c0     <= r0)     ? ex2f(s[jj][0]) : 0.f;
                float e1 = (c0 + 1 <= r0)     ? ex2f(s[jj][1]) : 0.f;
                float e2 = (c0     <= r0 + 8) ? ex2f(s[jj][2]) : 0.f;
                float e3 = (c0 + 1 <= r0 + 8) ? ex2f(s[jj][3]) : 0.f;
                l0 += e0 + e1;
                l1 += e2 + e3;
                pa[jj * 2 + 0] = packh2(e0, e1);
                pa[jj * 2 + 1] = packh2(e2, e3);
            }
            #pragma unroll
            for (int hj = 0; hj < 8; hj++) {
                uint32_t bv[2];
                const __half* vp = vs + (size_t)(hj * 8 + lr) * SKS + kt2 * 16 + lc * 2;
                bv[0] = *(const uint32_t*)vp;
                bv[1] = *(const uint32_t*)(vp + 8);
                mma16816(o[hj], pa, bv);
            }
        }
        __syncthreads();
        buf ^= 1;
    }

    l0 += __shfl_xor_sync(0xFFFFFFFFu, l0, 1);
    l0 += __shfl_xor_sync(0xFFFFFFFFu, l0, 2);
    l1 += __shfl_xor_sync(0xFFFFFFFFu, l1, 1);
    l1 += __shfl_xor_sync(0xFFFFFFFFu, l1, 2);

    const size_t pbase = ((size_t)((b * NQT + qt) * MAXCH + cI)) * QT;
    const int rl = wid * 16 + lr;
    if (lc == 0) {
        g_pl[pbase + rl]     = l0;
        g_pl[pbase + rl + 8] = l1;
    }
    #pragma unroll
    for (int hj = 0; hj < 8; hj++) {
        int h = hj * 8 + lc * 2;
        *(float2*)(g_po + (pbase + rl) * HH + h)     = make_float2(o[hj][0], o[hj][1]);
        *(float2*)(g_po + (pbase + rl + 8) * HH + h) = make_float2(o[hj][2], o[hj][3]);
    }
}

// ===========================================================================
// Combine: out = (sum_i o_i) / (sum_i l_i)
// ===========================================================================
__global__ void __launch_bounds__(128) combine_kernel(float* __restrict__ out)
{
    const int qt = blockIdx.x, b = blockIdx.y;
    const int tid = threadIdx.x;
    const int nch = qt / 4 + 1;

    const size_t pb = ((size_t)((b * NQT + qt) * MAXCH)) * QT + tid;
    float acc[HH];
    #pragma unroll
    for (int d = 0; d < HH; d++) acc[d] = 0.f;
    float L = 0.f;

    for (int i = 0; i < nch; i++) {
        const size_t pi = pb + (size_t)i * QT;
        L += g_pl[pi];
        const float4* po = (const float4*)(g_po + pi * HH);
        #pragma unroll
        for (int d4 = 0; d4 < 16; d4++) {
            float4 v = po[d4];
            acc[d4*4+0] += v.x; acc[d4*4+1] += v.y;
            acc[d4*4+2] += v.z; acc[d4*4+3] += v.w;
        }
    }
    const float invL = 1.f / L;
    float4* op = (float4*)(out + ((size_t)b * TT + qt * QT + tid) * HH);
    #pragma unroll
    for (int d4 = 0; d4 < 16; d4++)
        op[d4] = make_float4(acc[d4*4+0] * invL, acc[d4*4+1] * invL,
                             acc[d4*4+2] * invL, acc[d4*4+3] * invL);
}

// ===========================================================================
extern "C" void kernel_launch(void* const* d_in, const int* in_sizes, int n_in,
                              void* d_out, int out_size)
{
    const float* x  = (const float*)d_in[0];
    const float* Wk = (const float*)d_in[1];
    const float* Wq = (const float*)d_in[2];
    const float* Wv = (const float*)d_in[3];
    (void)in_sizes; (void)n_in; (void)out_size;

    prep_w<<<dim3(8, 3), 256>>>(Wk, Wq, Wv);
    proj_fused<<<BT / 64, 256>>>(x);
    attn_tc<<<dim3(MAXCH, NQT, BB), 256>>>();
    combine_kernel<<<dim3(NQT, BB), 128>>>((float*)d_out);
}

// round 6
// speedup vs baseline: 6.3359x; 1.1149x over previous
#include <cuda_runtime.h>
#include <cuda_fp16.h>
#include <cstdint>
#include <cstddef>

// ---------------- problem constants ----------------
#define BB    4
#define TT    4096
#define CC    512
#define HH    64
#define BT    (BB * TT)
#define QT    128                 // queries per attention block
#define NQT   (TT / QT)           // 32
#define CHUNK 512
#define MAXCH (TT / CHUNK)        // 8
#define KTILE 64                  // keys per tile

// log2(e) / sqrt(512)  (folded into Wk -> scores arrive in base-2 domain)
#define SC2   0.063766600930416f

#define SKS   72                  // halfs per smem row (144 B, conflict-free)

// ---------------- global scratch ----------------
__device__ __half g_K[BT * HH];               // x @ (Wk*SC2)  (query role)
__device__ __half g_Q[BT * HH];               // x @ Wq        (key role)
__device__ __half g_Vt[(size_t)BB * HH * TT]; // (x @ Wv)^T : [b][h][t]
__device__ __half g_Wt[192 * CC];             // fp16 W^T: [outcol 0-63=K,64-127=Q,128-191=V][c]
__device__ float  g_po[(size_t)BB * NQT * MAXCH * QT * HH];
__device__ float  g_pl[BB * NQT * MAXCH * QT];

// ---------------- helpers ----------------
__device__ __forceinline__ float ex2f(float x) {
    float y; asm("ex2.approx.ftz.f32 %0, %1;" : "=f"(y) : "f"(x)); return y;
}
__device__ __forceinline__ uint32_t smem_u32(const void* p) {
    uint32_t a;
    asm("{ .reg .u64 t; cvta.to.shared.u64 t, %1; cvt.u32.u64 %0, t; }" : "=r"(a) : "l"(p));
    return a;
}
__device__ __forceinline__ void mma16816(float* d, const uint32_t* a, const uint32_t* b) {
    asm volatile(
        "mma.sync.aligned.m16n8k16.row.col.f32.f16.f16.f32 "
        "{%0,%1,%2,%3}, {%4,%5,%6,%7}, {%8,%9}, {%0,%1,%2,%3};"
        : "+f"(d[0]), "+f"(d[1]), "+f"(d[2]), "+f"(d[3])
        : "r"(a[0]), "r"(a[1]), "r"(a[2]), "r"(a[3]), "r"(b[0]), "r"(b[1]));
}
__device__ __forceinline__ void cpa16(uint32_t dst, const void* src) {
    asm volatile("cp.async.cg.shared.global [%0], [%1], 16;" :: "r"(dst), "l"(src));
}
#define CP_COMMIT() asm volatile("cp.async.commit_group;" ::: "memory")
#define CP_WAIT(n)  asm volatile("cp.async.wait_group %0;" :: "n"(n) : "memory")

__device__ __forceinline__ uint32_t packh2(float a, float b) {
    __half2 h = __floats2half2_rn(a, b);
    return *(uint32_t*)&h;
}

// ===========================================================================
// prep_w: fp32 W[c][h] -> fp16 g_Wt[m*64+h][c], SC2 folded into Wk.
// ===========================================================================
__global__ void __launch_bounds__(256) prep_w(
    const float* __restrict__ Wk,
    const float* __restrict__ Wq,
    const float* __restrict__ Wv)
{
    const int m = blockIdx.y;
    const int cb = blockIdx.x * 64;
    const float* W = (m == 0) ? Wk : ((m == 1) ? Wq : Wv);
    const float sc = (m == 0) ? SC2 : 1.0f;
    for (int i = threadIdx.x; i < 4096; i += 256) {
        int c = i >> 6, h = i & 63;
        g_Wt[(size_t)(m * 64 + h) * CC + cb + c] =
            __float2half_rn(W[(size_t)(cb + c) * HH + h] * sc);
    }
}

// ===========================================================================
// proj_fused: block = 64 rows x 192 cols (K|Q|V), 256 threads = 8 warps.
// ===========================================================================
__global__ void __launch_bounds__(256) proj_fused(const float* __restrict__ x)
{
    __shared__ __half Xs[64 * SKS];    // [row][c]
    __shared__ __half Ws[192 * SKS];   // [outcol][c]

    const int tid = threadIdx.x, wid = tid >> 5, lane = tid & 31;
    const int lr = lane >> 2, lc = lane & 3;
    const int rg = wid >> 1, ch = wid & 1;
    const int row0 = blockIdx.x * 64;

    float o[12][4];
    #pragma unroll
    for (int j = 0; j < 12; j++)
        #pragma unroll
        for (int i = 0; i < 4; i++) o[j][i] = 0.f;

    const uint32_t wsa = smem_u32(Ws);

    for (int kc = 0; kc < 8; kc++) {
        const int kb = kc * 64;
        __syncthreads();
        #pragma unroll
        for (int it = 0; it < 6; it++) {
            int u = tid + it * 256;
            int row = u >> 3, seg = u & 7;
            cpa16(wsa + ((uint32_t)row * SKS + seg * 8) * 2,
                  g_Wt + (size_t)row * CC + kb + seg * 8);
        }
        #pragma unroll
        for (int it = 0; it < 4; it++) {
            int i = tid + it * 256;
            int r = i >> 4, c4 = i & 15;
            float4 v = *(const float4*)(x + (size_t)(row0 + r) * CC + kb + c4 * 4);
            *(uint2*)((char*)Xs + ((size_t)r * SKS + c4 * 4) * 2) =
                make_uint2(packh2(v.x, v.y), packh2(v.z, v.w));
        }
        CP_COMMIT(); CP_WAIT(0);
        __syncthreads();

        const int xrow = rg * 16 + lr;
        #pragma unroll
        for (int kk = 0; kk < 4; kk++) {
            uint32_t a[4];
            const __half* xp = Xs + (size_t)xrow * SKS + kk * 16 + lc * 2;
            a[0] = *(const uint32_t*)xp;
            a[1] = *(const uint32_t*)(xp + 8 * SKS);
            a[2] = *(const uint32_t*)(xp + 8);
            a[3] = *(const uint32_t*)(xp + 8 * SKS + 8);
            #pragma unroll
            for (int hj = 0; hj < 12; hj++) {
                uint32_t b[2];
                const __half* wp = Ws + (size_t)(ch * 96 + hj * 8 + lr) * SKS + kk * 16 + lc * 2;
                b[0] = *(const uint32_t*)wp;
                b[1] = *(const uint32_t*)(wp + 8);
                mma16816(o[hj], a, b);
            }
        }
    }

    const int r = row0 + rg * 16 + lr;
    const int bb = r >> 12, t = r & 4095;
    #pragma unroll
    for (int hj = 0; hj < 12; hj++) {
        const int g = ch * 96 + hj * 8;
        const int h2 = (g & 63) + lc * 2;
        if (g < 64) {
            *(uint32_t*)(g_K + (size_t)r * HH + h2)       = packh2(o[hj][0], o[hj][1]);
            *(uint32_t*)(g_K + (size_t)(r + 8) * HH + h2) = packh2(o[hj][2], o[hj][3]);
        } else if (g < 128) {
            *(uint32_t*)(g_Q + (size_t)r * HH + h2)       = packh2(o[hj][0], o[hj][1]);
            *(uint32_t*)(g_Q + (size_t)(r + 8) * HH + h2) = packh2(o[hj][2], o[hj][3]);
        } else {
            g_Vt[((size_t)bb * HH + h2) * TT + t]         = __float2half_rn(o[hj][0]);
            g_Vt[((size_t)bb * HH + h2 + 1) * TT + t]     = __float2half_rn(o[hj][1]);
            g_Vt[((size_t)bb * HH + h2) * TT + t + 8]     = __float2half_rn(o[hj][2]);
            g_Vt[((size_t)bb * HH + h2 + 1) * TT + t + 8] = __float2half_rn(o[hj][3]);
        }
    }
}

// ===========================================================================
// Attention partial: grid (MAXCH, NQT, BB), 256 threads (8 warps x 16 rows).
// ===========================================================================
__global__ void __launch_bounds__(256) attn_tc()
{
    const int cI = blockIdx.x, qt = blockIdx.y, b = blockIdx.z;
    const int qb = qt * QT;
    const int kstart = cI * CHUNK;
    if (kstart >= qb + QT) return;
    const int kend = min(kstart + CHUNK, qb + QT);

    __shared__ __half Ks[2][64 * SKS];   // [key][h]
    __shared__ __half Vs[2][64 * SKS];   // [h][key]

    const int tid = threadIdx.x, wid = tid >> 5, lane = tid & 31;
    const int lr = lane >> 2, lc = lane & 3;
    const int r0 = qb + wid * 16 + lr;

    uint32_t aq[4][4];
    {
        const __half* q0 = g_K + ((size_t)b * TT + r0) * HH;
        #pragma unroll
        for (int kk = 0; kk < 4; kk++) {
            int h0 = kk * 16 + lc * 2;
            aq[kk][0] = *(const uint32_t*)(q0 + h0);
            aq[kk][1] = *(const uint32_t*)(q0 + 8 * HH + h0);
            aq[kk][2] = *(const uint32_t*)(q0 + h0 + 8);
            aq[kk][3] = *(const uint32_t*)(q0 + 8 * HH + h0 + 8);
        }
    }

    float o[8][4];
    #pragma unroll
    for (int j = 0; j < 8; j++)
        #pragma unroll
        for (int i = 0; i < 4; i++) o[j][i] = 0.f;
    float l0 = 0.f, l1 = 0.f;

    const uint32_t ksa0 = smem_u32(Ks[0]), ksa1 = smem_u32(Ks[1]);
    const uint32_t vsa0 = smem_u32(Vs[0]), vsa1 = smem_u32(Vs[1]);

    auto prefetch = [&](int buf, int kb) {
        const uint32_t ka = buf ? ksa1 : ksa0;
        const uint32_t va = buf ? vsa1 : vsa0;
        #pragma unroll
        for (int it = 0; it < 2; it++) {
            int i = tid + it * 256;
            int row = i >> 3, seg = i & 7;
            cpa16(ka + ((uint32_t)row * SKS + seg * 8) * 2,
                  g_Q + ((size_t)b * TT + kb + row) * HH + seg * 8);
            cpa16(va + ((uint32_t)row * SKS + seg * 8) * 2,
                  g_Vt + ((size_t)b * HH + row) * TT + kb + seg * 8);
        }
    };

    prefetch(0, kstart);
    CP_COMMIT();

    int buf = 0;
    for (int kb = kstart; kb < kend; kb += KTILE) {
        const bool havenext = (kb + KTILE < kend);
        if (havenext) { prefetch(buf ^ 1, kb + KTILE); CP_COMMIT(); CP_WAIT(1); }
        else          { CP_WAIT(0); }
        __syncthreads();

        const __half* ks = Ks[buf];
        const __half* vs = Vs[buf];

        #pragma unroll
        for (int kt2 = 0; kt2 < 4; kt2++) {
            float s[2][4];
            #pragma unroll
            for (int jj = 0; jj < 2; jj++) {
                s[jj][0] = 0.f; s[jj][1] = 0.f; s[jj][2] = 0.f; s[jj][3] = 0.f;
                const int j = kt2 * 2 + jj;
                #pragma unroll
                for (int kk = 0; kk < 4; kk++) {
                    uint32_t bk[2];
                    const __half* kp = ks + (size_t)(j * 8 + lr) * SKS + kk * 16 + lc * 2;
                    bk[0] = *(const uint32_t*)kp;
                    bk[1] = *(const uint32_t*)(kp + 8);
                    mma16816(s[jj], aq[kk], bk);
                }
            }
            uint32_t pa[4];
            #pragma unroll
            for (int jj = 0; jj < 2; jj++) {
                const int c0 = kb + kt2 * 16 + jj * 8 + lc * 2;
                float e0 = (c0     <= r0)     ? ex2f(s[jj][0]) : 0.f;
                float e1 = (c0 + 1 <= r0)     ? ex2f(s[jj][1]) : 0.f;
                float e2 = (c0     <= r0 + 8) ? ex2f(s[jj][2]) : 0.f;
                float e3 = (c0 + 1 <= r0 + 8) ? ex2f(s[jj][3]) : 0.f;
                l0 += e0 + e1;
                l1 += e2 + e3;
                pa[jj * 2 + 0] = packh2(e0, e1);
                pa[jj * 2 + 1] = packh2(e2, e3);
            }
            #pragma unroll
            for (int hj = 0; hj < 8; hj++) {
                uint32_t bv[2];
                const __half* vp = vs + (size_t)(hj * 8 + lr) * SKS + kt2 * 16 + lc * 2;
                bv[0] = *(const uint32_t*)vp;
                bv[1] = *(const uint32_t*)(vp + 8);
                mma16816(o[hj], pa, bv);
            }
        }
        __syncthreads();
        buf ^= 1;
    }

    l0 += __shfl_xor_sync(0xFFFFFFFFu, l0, 1);
    l0 += __shfl_xor_sync(0xFFFFFFFFu, l0, 2);
    l1 += __shfl_xor_sync(0xFFFFFFFFu, l1, 1);
    l1 += __shfl_xor_sync(0xFFFFFFFFu, l1, 2);

    const size_t pbase = ((size_t)((b * NQT + qt) * MAXCH + cI)) * QT;
    const int rl = wid * 16 + lr;
    if (lc == 0) {
        g_pl[pbase + rl]     = l0;
        g_pl[pbase + rl + 8] = l1;
    }
    #pragma unroll
    for (int hj = 0; hj < 8; hj++) {
        int h = hj * 8 + lc * 2;
        *(float2*)(g_po + (pbase + rl) * HH + h)     = make_float2(o[hj][0], o[hj][1]);
        *(float2*)(g_po + (pbase + rl + 8) * HH + h) = make_float2(o[hj][2], o[hj][3]);
    }
}

// ===========================================================================
// Combine v2: one thread per (row, 4 output floats).
// grid 1024 x block 256 = 262144 threads; row = gid>>4, d4 = gid&15.
// ===========================================================================
__global__ void __launch_bounds__(256) combine_kernel(float* __restrict__ out)
{
    const int gid = blockIdx.x * 256 + threadIdx.x;
    const int row = gid >> 4;            // global row in [0, BT)
    const int d4  = gid & 15;            // which float4 of the 64-wide head dim
    const int b   = row >> 12;
    const int tl  = row & 4095;
    const int qt  = tl >> 7;             // query tile
    const int ql  = tl & 127;            // row within tile
    const int nch = (qt >> 2) + 1;       // chunks touching this tile

    const size_t pb = ((size_t)((b * NQT + qt) * MAXCH)) * QT + ql;

    float4 acc = make_float4(0.f, 0.f, 0.f, 0.f);
    float L = 0.f;
    #pragma unroll 4
    for (int i = 0; i < nch; i++) {
        const size_t pi = pb + (size_t)i * QT;
        L += g_pl[pi];
        float4 v = *(const float4*)(g_po + pi * HH + d4 * 4);
        acc.x += v.x; acc.y += v.y; acc.z += v.z; acc.w += v.w;
    }
    const float invL = 1.f / L;
    *(float4*)(out + (size_t)row * HH + d4 * 4) =
        make_float4(acc.x * invL, acc.y * invL, acc.z * invL, acc.w * invL);
}

// ===========================================================================
extern "C" void kernel_launch(void* const* d_in, const int* in_sizes, int n_in,
                              void* d_out, int out_size)
{
    const float* x  = (const float*)d_in[0];
    const float* Wk = (const float*)d_in[1];
    const float* Wq = (const float*)d_in[2];
    const float* Wv = (const float*)d_in[3];
    (void)in_sizes; (void)n_in; (void)out_size;

    prep_w<<<dim3(8, 3), 256>>>(Wk, Wq, Wv);
    proj_fused<<<BT / 64, 256>>>(x);
    attn_tc<<<dim3(MAXCH, NQT, BB), 256>>>();
    combine_kernel<<<(BT * 16) / 256, 256>>>((float*)d_out);
}